// round 7
// baseline (speedup 1.0000x reference)
#include <cuda_runtime.h>

// ---------------------------------------------------------------------------
// H3 block, chunked state-passing formulation.
// B=1, S=1024, D=512, HEADS=8, DH=64, N=64 modes, DT=0.1, chunk L=64.
// ---------------------------------------------------------------------------

#define SQ 1024
#define DD 512

__device__ float  g_Q [SQ*DD];
__device__ float  g_K0[SQ*DD];
__device__ float  g_K [SQ*DD];
__device__ float  g_V [SQ*DD];
__device__ float  g_Ot[DD*SQ];          // pre-WO output, transposed [d][s]
__device__ float2 g_dApow[65][64];      // dA^p per mode
__device__ float  g_Kd[32768*64];       // truncated SSM kernel taps, [c][d]

typedef unsigned long long u64t;

__device__ __forceinline__ u64t pack2(float lo, float hi) {
    u64t r; asm("mov.b64 %0, {%1,%2};" : "=l"(r) : "f"(lo), "f"(hi)); return r;
}
__device__ __forceinline__ void unpack2(u64t v, float& lo, float& hi) {
    asm("mov.b64 {%0,%1}, %2;" : "=f"(lo), "=f"(hi) : "l"(v));
}
__device__ __forceinline__ u64t fma2(u64t a, u64t b, u64t c) {
    u64t d; asm("fma.rn.f32x2 %0, %1, %2, %3;" : "=l"(d) : "l"(a), "l"(b), "l"(c)); return d;
}

// ---------------------------------------------------------------------------
// GEMM 1: C[1024,512] = A @ W^T  (x3 via grid.z)
// ---------------------------------------------------------------------------
__global__ __launch_bounds__(256) void gemm_qkv(
    const float* __restrict__ A,
    const float* __restrict__ WQ, const float* __restrict__ WK,
    const float* __restrict__ WV)
{
    const float* W = (blockIdx.z == 0) ? WQ : (blockIdx.z == 1) ? WK : WV;
    float*       C = (blockIdx.z == 0) ? g_Q : (blockIdx.z == 1) ? g_K0 : g_V;

    __shared__ __align__(16) float As[16][64];
    __shared__ __align__(16) float Bs[16][64];

    const int t  = threadIdx.x;
    const int tx = t & 15, ty = t >> 4;
    const int m0 = blockIdx.y * 64, n0 = blockIdx.x * 64;
    const int lr = t >> 2, lk = (t & 3) * 4;

    u64t acc2[4][2] = {};

    for (int k0 = 0; k0 < 512; k0 += 16) {
        float4 av = *(const float4*)(A + (m0 + lr) * 512 + k0 + lk);
        float4 bv = *(const float4*)(W + (n0 + lr) * 512 + k0 + lk);
        __syncthreads();
        As[lk+0][lr] = av.x; As[lk+1][lr] = av.y; As[lk+2][lr] = av.z; As[lk+3][lr] = av.w;
        Bs[lk+0][lr] = bv.x; Bs[lk+1][lr] = bv.y; Bs[lk+2][lr] = bv.z; Bs[lk+3][lr] = bv.w;
        __syncthreads();
#pragma unroll
        for (int k = 0; k < 16; k++) {
            float4 a4 = *(const float4*)&As[k][ty * 4];
            float4 b4 = *(const float4*)&Bs[k][tx * 4];
            const u64t b01 = pack2(b4.x, b4.y);
            const u64t b23 = pack2(b4.z, b4.w);
            float ar[4] = {a4.x, a4.y, a4.z, a4.w};
#pragma unroll
            for (int e = 0; e < 4; e++) {
                const u64t ae = pack2(ar[e], ar[e]);
                acc2[e][0] = fma2(ae, b01, acc2[e][0]);
                acc2[e][1] = fma2(ae, b23, acc2[e][1]);
            }
        }
    }
#pragma unroll
    for (int e = 0; e < 4; e++) {
        float4 v;
        unpack2(acc2[e][0], v.x, v.y);
        unpack2(acc2[e][1], v.z, v.w);
        *(float4*)(C + (m0 + ty * 4 + e) * 512 + n0 + tx * 4) = v;
    }
}

// ---------------------------------------------------------------------------
// Shift-SSM FIR on K (64 taps + skip)
// ---------------------------------------------------------------------------
__global__ __launch_bounds__(256) void shift_conv(
    const float* __restrict__ Cs, const float* __restrict__ Ds)
{
    const int d = blockIdx.x;
    __shared__ float taps[64];
    __shared__ float col[1024];
    const int t = threadIdx.x;
    if (t < 64) taps[t] = Cs[d * 64 + t];
    for (int s = t; s < 1024; s += 256) col[s] = g_K0[s * 512 + d];
    __syncthreads();
    const float dsv = Ds[d];
    for (int s = t; s < 1024; s += 256) {
        float acc = dsv * col[s];
        const int tmax = (s < 63) ? s : 63;
        for (int tt = 0; tt <= tmax; tt++) acc += taps[tt] * col[s - tt];
        g_K[s * 512 + d] = acc;
    }
}

// ---------------------------------------------------------------------------
// Precompute dA powers: g_dApow[p][n] = dA[n]^p, p=0..64
// ---------------------------------------------------------------------------
__global__ void precomp(const float* __restrict__ Are, const float* __restrict__ Aim)
{
    const int n = threadIdx.x;
    const float are = Are[n], aim = Aim[n];
    const float dre = 1.f - 0.05f * are, dim = -0.05f * aim;
    const float nre = 1.f + 0.05f * are, nim = 0.05f * aim;
    const float inv = 1.f / (dre * dre + dim * dim);
    const float dare = (nre * dre + nim * dim) * inv;
    const float daim = (nim * dre - nre * dim) * inv;
    float pre = 1.f, pim = 0.f;
    for (int p = 0; p <= 64; p++) {
        g_dApow[p][n] = make_float2(pre, pim);
        const float tr = pre * dare - pim * daim;
        pim = pre * daim + pim * dare;
        pre = tr;
    }
}

// ---------------------------------------------------------------------------
// Kd taps: g_Kd[c][d] = Re( sum_n 2*CB[c,n] * dA[n]^d ), d = 0..63
// grid 512 (64 channels each), 256 threads (thread = (c-offset, d-quarter))
// ---------------------------------------------------------------------------
__global__ __launch_bounds__(256) void kd_kernel(
    const float* __restrict__ Are, const float* __restrict__ Aim,
    const float* __restrict__ Cre, const float* __restrict__ Cim)
{
    __shared__ float2 pw[64][64];   // [d][n]
    const int t = threadIdx.x;
    for (int e = t; e < 4096; e += 256) {
        const int d = e >> 6, n = e & 63;
        pw[d][n] = g_dApow[d][n];
    }
    __syncthreads();

    const int c = blockIdx.x * 64 + (t & 63);
    const int q = t >> 6;                 // d-range q*16 .. q*16+15
    float acc[16];
#pragma unroll
    for (int d = 0; d < 16; d++) acc[d] = 0.f;

    for (int n = 0; n < 64; n++) {
        const float are = Are[n], aim = Aim[n];
        const float dre = 1.f - 0.05f * are, dim = -0.05f * aim;
        const float inv = 1.f / (dre * dre + dim * dim);
        const float dbre = 0.1f * dre * inv, dbim = -0.1f * dim * inv;
        const float cr = Cre[c * 64 + n], ci = Cim[c * 64 + n];
        const float c2re = 2.f * (cr * dbre - ci * dbim);
        const float c2im = 2.f * (cr * dbim + ci * dbre);
#pragma unroll
        for (int d = 0; d < 16; d++) {
            const float2 w = pw[q * 16 + d][n];
            acc[d] += c2re * w.x - c2im * w.y;
        }
    }
    for (int d = 0; d < 16; d++) g_Kd[c * 64 + q * 16 + d] = acc[d];
}

// ---------------------------------------------------------------------------
// Fused chunked S4D + Q contraction. grid 512 = (h, j), 512 threads.
// Mapping A (Z/state phases): iZ = t>>3, oct = t&7 (8 modes/thread).
// Mapping B (H/intra phases):  iH = t&63, sq = t>>6 (8 s'/thread).
// Per chunk: Z GEMM (u @ M), P=2CB*z0 + state update, H GEMM (P @ W^T),
// per-channel Toeplitz intra, skip, Q contraction.
// ---------------------------------------------------------------------------

// dynamic smem layout (bytes)
#define OFF_POW 0                         // float2[65][64]  33280
#define OFF_WPK 33280                     // float4[64][32]  32768
#define OFF_KD  66048                     // float[64][65]   16640
#define OFF_US  82688                     // float[64][65]   16640
#define OFF_P   99328                     // float2[64][65]  33280
#define OFF_YW  132608                    // float[64][65]   16640
#define OFF_QS  149248                    // float[64][65]   16640
#define OFF_V   165888                    // float[64]         256
#define SMEM_CHUNK 166144

__global__ __launch_bounds__(512) void chunk_s4d(
    const float* __restrict__ Are, const float* __restrict__ Aim,
    const float* __restrict__ Cre, const float* __restrict__ Cim,
    const float* __restrict__ Dd)
{
    extern __shared__ __align__(16) char smemRaw[];
    float2* sPow = (float2*)(smemRaw + OFF_POW);   // [p*64 + n]
    float4* sWpk = (float4*)(smemRaw + OFF_WPK);   // [n*32 + pr]
    float*  sKd  = (float*) (smemRaw + OFF_KD);    // [i*65 + d]
    float*  sUs  = (float*) (smemRaw + OFF_US);    // [i*65 + t']
    float2* sP   = (float2*)(smemRaw + OFF_P);     // [n*65 + i]
    float*  sYw  = (float*) (smemRaw + OFF_YW);    // [s'*65 + i]
    float*  sQ   = (float*) (smemRaw + OFF_QS);    // [s'*65 + i]
    float*  sV   = (float*) (smemRaw + OFF_V);

    const int b = blockIdx.x;
    const int h = b >> 6, j = b & 63;
    const int t = threadIdx.x;
    const int iZ = t >> 3, oct = t & 7;
    const int iH = t & 63, sq = t >> 6;
    const int sBase = sq * 8;

    // ---- setup: tables ----
    for (int e = t; e < 65 * 64; e += 512) {
        const int p = e >> 6, n = e & 63;
        sPow[p * 64 + n] = g_dApow[p][n];
    }
    {   // Kd tile for this block's 64 channels
        for (int e = t; e < 4096; e += 512) {
            const int i = e >> 6, d = e & 63;
            sKd[i * 65 + d] = g_Kd[(h * 4096 + i * 64 + j) * 64 + d];
        }
    }
    __syncthreads();
    // Wpack[n][pr] = (re(2pr), re(2pr+1), im(2pr), im(2pr+1)), W(s')=dA^{s'+1}
    for (int e = t; e < 64 * 32; e += 512) {
        const int n = e >> 5, pr = e & 31;
        const float2 a = sPow[(2 * pr + 1) * 64 + n];
        const float2 c = sPow[(2 * pr + 2) * 64 + n];
        sWpk[n * 32 + pr] = make_float4(a.x, c.x, a.y, c.y);
    }

    // ---- per-thread coefficients (mapping A): 2*CB for 8 modes ----
    const int cZ = h * 4096 + iZ * 64 + j;
    float C2re[8], C2im[8], z0re[8], z0im[8];
#pragma unroll
    for (int k = 0; k < 8; k++) {
        const int n = oct * 8 + k;
        const float are = Are[n], aim = Aim[n];
        const float dre = 1.f - 0.05f * are, dim = -0.05f * aim;
        const float inv = 1.f / (dre * dre + dim * dim);
        const float dbre = 0.1f * dre * inv, dbim = -0.1f * dim * inv;
        const float cr = Cre[cZ * 64 + n], ci = Cim[cZ * 64 + n];
        C2re[k] = 2.f * (cr * dbre - ci * dbim);
        C2im[k] = 2.f * (cr * dbim + ci * dbre);
        z0re[k] = 0.f; z0im[k] = 0.f;
    }
    const float Ddv = Dd[h * 4096 + iH * 64 + j];
    __syncthreads();

    // ---- chunk loop ----
    for (int ch = 0; ch < 16; ch++) {
        const int s0 = ch * 64;

        if (t < 64) sV[t] = g_V[(s0 + t) * 512 + h * 64 + j];
        __syncthreads();   // A

        // build u tile (transposed) and load Q tile
#pragma unroll
        for (int q8 = 0; q8 < 8; q8++) {
            const int idx = t + q8 * 512;
            const int i = idx & 63, tp = idx >> 6;
            sUs[i * 65 + tp] = g_K[(s0 + tp) * 512 + h * 64 + i] * sV[tp];
            sQ[tp * 65 + i] = g_Q[(s0 + tp) * 512 + h * 64 + i];
        }
        __syncthreads();   // B

        // ---- Z GEMM: Z_in[n] = sum_t' u[iZ,t'] * dA^{63-t'}[n] ----
        u64t Zacc[8] = {0,0,0,0,0,0,0,0};
#pragma unroll 4
        for (int tp = 0; tp < 64; tp++) {
            const float u = sUs[iZ * 65 + tp];
            const u64t u2 = pack2(u, u);
            const float2* row = sPow + (63 - tp) * 64 + oct * 8;
#pragma unroll
            for (int k4 = 0; k4 < 4; k4++) {
                const float4 m = *(const float4*)(row + 2 * k4);
                Zacc[2*k4+0] = fma2(u2, pack2(m.x, m.y), Zacc[2*k4+0]);
                Zacc[2*k4+1] = fma2(u2, pack2(m.z, m.w), Zacc[2*k4+1]);
            }
        }

        // ---- P = (2CB) * z0 (old state), then z0 <- dA^64*z0 + Z_in ----
#pragma unroll
        for (int k = 0; k < 8; k++) {
            const float pre = C2re[k] * z0re[k] - C2im[k] * z0im[k];
            const float pim = C2re[k] * z0im[k] + C2im[k] * z0re[k];
            sP[(oct * 8 + k) * 65 + iZ] = make_float2(pre, pim);
            const float2 dal = sPow[64 * 64 + oct * 8 + k];
            float zr, zi; unpack2(Zacc[k], zr, zi);
            const float nr = dal.x * z0re[k] - dal.y * z0im[k] + zr;
            const float ni = dal.x * z0im[k] + dal.y * z0re[k] + zi;
            z0re[k] = nr; z0im[k] = ni;
        }
        __syncthreads();   // C

        // ---- H GEMM: hist[iH, s'] = sum_n Re(P[iH,n] * dA^{s'+1}[n]) ----
        u64t Hacc[4] = {0,0,0,0};
#pragma unroll 2
        for (int n = 0; n < 64; n++) {
            const float2 p = sP[n * 65 + iH];
            const u64t pre2 = pack2(p.x, p.x);
            const u64t npim2 = pack2(-p.y, -p.y);
            const float4* wrow = sWpk + n * 32 + sq * 4;
#pragma unroll
            for (int q4 = 0; q4 < 4; q4++) {
                const float4 w = wrow[q4];
                Hacc[q4] = fma2(pre2, pack2(w.x, w.y), Hacc[q4]);
                Hacc[q4] = fma2(npim2, pack2(w.z, w.w), Hacc[q4]);
            }
        }
        float yv[8];
#pragma unroll
        for (int q4 = 0; q4 < 4; q4++) unpack2(Hacc[q4], yv[2*q4], yv[2*q4+1]);

        // ---- intra-chunk Toeplitz: += sum_{t'<=s'} Kd[s'-t'] * u[t'] ----
        const float* kdr = sKd + iH * 65;
        const float* usr = sUs + iH * 65;
        for (int tp = 0; tp < sBase; tp++) {
            const float u = usr[tp];
#pragma unroll
            for (int m = 0; m < 8; m++) yv[m] += kdr[sBase + m - tp] * u;
        }
#pragma unroll
        for (int tp2 = 0; tp2 < 8; tp2++) {
            const int tp = sBase + tp2;
            const float u = usr[tp];
#pragma unroll
            for (int m = 0; m < 8; m++)
                if (m >= tp2) yv[m] += kdr[m - tp2] * u;
        }

        // ---- skip + stage y ----
#pragma unroll
        for (int m = 0; m < 8; m++) {
            const int sp = sBase + m;
            sYw[sp * 65 + iH] = yv[m] + Ddv * usr[sp];
        }
        __syncthreads();   // D

        // ---- Q contraction: O[s'] = sum_i Q[s',i] * y[i,s'] ----
        if (t < 64) {
            const float* qr = sQ + t * 65;
            const float* yr = sYw + t * 65;
            float o = 0.f;
#pragma unroll 8
            for (int i = 0; i < 64; i++) o += qr[i] * yr[i];
            g_Ot[(h * 64 + j) * 1024 + s0 + t] = o;
        }
    }
}

// ---------------------------------------------------------------------------
// GEMM 2: out[s,n] = sum_k g_Ot[k][s] * WO[n,k]
// ---------------------------------------------------------------------------
__global__ __launch_bounds__(256) void gemm_out(
    const float* __restrict__ WO, float* __restrict__ out)
{
    __shared__ __align__(16) float As[16][64];
    __shared__ __align__(16) float Bs[16][64];

    const int t  = threadIdx.x;
    const int tx = t & 15, ty = t >> 4;
    const int m0 = blockIdx.y * 64, n0 = blockIdx.x * 64;
    const int lr = t >> 2, lk = (t & 3) * 4;
    const int kk = t >> 4, mm = (t & 15) * 4;

    u64t acc2[4][2] = {};

    for (int k0 = 0; k0 < 512; k0 += 16) {
        float4 av = *(const float4*)(g_Ot + (k0 + kk) * 1024 + m0 + mm);
        float4 bv = *(const float4*)(WO + (n0 + lr) * 512 + k0 + lk);
        __syncthreads();
        *(float4*)&As[kk][mm] = av;
        Bs[lk+0][lr] = bv.x; Bs[lk+1][lr] = bv.y; Bs[lk+2][lr] = bv.z; Bs[lk+3][lr] = bv.w;
        __syncthreads();
#pragma unroll
        for (int k = 0; k < 16; k++) {
            float4 a4 = *(const float4*)&As[k][ty * 4];
            float4 b4 = *(const float4*)&Bs[k][tx * 4];
            const u64t b01 = pack2(b4.x, b4.y);
            const u64t b23 = pack2(b4.z, b4.w);
            float ar[4] = {a4.x, a4.y, a4.z, a4.w};
#pragma unroll
            for (int e = 0; e < 4; e++) {
                const u64t ae = pack2(ar[e], ar[e]);
                acc2[e][0] = fma2(ae, b01, acc2[e][0]);
                acc2[e][1] = fma2(ae, b23, acc2[e][1]);
            }
        }
    }
#pragma unroll
    for (int e = 0; e < 4; e++) {
        float4 v;
        unpack2(acc2[e][0], v.x, v.y);
        unpack2(acc2[e][1], v.z, v.w);
        *(float4*)(out + (m0 + ty * 4 + e) * 512 + n0 + tx * 4) = v;
    }
}

// ---------------------------------------------------------------------------
extern "C" void kernel_launch(void* const* d_in, const int* in_sizes, int n_in,
                              void* d_out, int out_size)
{
    (void)in_sizes; (void)n_in; (void)out_size;
    const float* x   = (const float*)d_in[0];
    const float* WQ  = (const float*)d_in[1];
    const float* WK  = (const float*)d_in[2];
    const float* WV  = (const float*)d_in[3];
    const float* WO  = (const float*)d_in[4];
    const float* Cs  = (const float*)d_in[5];
    const float* Ds  = (const float*)d_in[6];
    const float* Are = (const float*)d_in[7];
    const float* Aim = (const float*)d_in[8];
    const float* Cre = (const float*)d_in[9];
    const float* Cim = (const float*)d_in[10];
    const float* Ddg = (const float*)d_in[11];

    static int smem_set = 0;
    if (!smem_set) {
        cudaFuncSetAttribute(chunk_s4d,
                             cudaFuncAttributeMaxDynamicSharedMemorySize,
                             SMEM_CHUNK);
        smem_set = 1;
    }

    gemm_qkv  <<<dim3(8, 16, 3), 256>>>(x, WQ, WK, WV);
    precomp   <<<1, 64>>>(Are, Aim);
    shift_conv<<<512, 256>>>(Cs, Ds);
    kd_kernel <<<512, 256>>>(Are, Aim, Cre, Cim);
    chunk_s4d <<<512, 512, SMEM_CHUNK>>>(Are, Aim, Cre, Cim, Ddg);
    gemm_out  <<<dim3(8, 16), 256>>>(WO, (float*)d_out);
}

// round 10
// speedup vs baseline: 5.2827x; 5.2827x over previous
#include <cuda_runtime.h>

// ---------------------------------------------------------------------------
// H3 block: Q/K/V proj -> shift-SSM FIR on K -> per-head KV outer product ->
// S4D diagonal SSM (linear recurrence scan, packed f32x2) -> Q contraction ->
// output projection.  B=1, S=1024, D=512, HEADS=8, DH=64, N=64, DT=0.1
// ---------------------------------------------------------------------------

#define SQ   1024
#define DD   512

__device__ float g_Q [SQ*DD];
__device__ float g_K0[SQ*DD];
__device__ float g_K [SQ*DD];
__device__ float g_V [SQ*DD];
__device__ float g_Ot[DD*SQ];   // pre-WO output, transposed [d][s]

typedef unsigned long long u64t;

__device__ __forceinline__ u64t pack2(float lo, float hi) {
    u64t r; asm("mov.b64 %0, {%1,%2};" : "=l"(r) : "f"(lo), "f"(hi)); return r;
}
__device__ __forceinline__ void unpack2(u64t v, float& lo, float& hi) {
    asm("mov.b64 {%0,%1}, %2;" : "=f"(lo), "=f"(hi) : "l"(v));
}
__device__ __forceinline__ u64t fma2(u64t a, u64t b, u64t c) {
    u64t d; asm("fma.rn.f32x2 %0, %1, %2, %3;" : "=l"(d) : "l"(a), "l"(b), "l"(c)); return d;
}
__device__ __forceinline__ u64t mul2(u64t a, u64t b) {
    u64t d; asm("mul.rn.f32x2 %0, %1, %2;" : "=l"(d) : "l"(a), "l"(b)); return d;
}

// ---------------------------------------------------------------------------
// GEMM 1: C[1024,512] = A @ W^T  (x3 via grid.z), 64x64 tile, packed-f32x2 FMA
// ---------------------------------------------------------------------------
__global__ __launch_bounds__(256) void gemm_qkv(
    const float* __restrict__ A,
    const float* __restrict__ WQ, const float* __restrict__ WK,
    const float* __restrict__ WV)
{
    const float* W = (blockIdx.z == 0) ? WQ : (blockIdx.z == 1) ? WK : WV;
    float*       C = (blockIdx.z == 0) ? g_Q : (blockIdx.z == 1) ? g_K0 : g_V;

    __shared__ __align__(16) float As[16][64];
    __shared__ __align__(16) float Bs[16][64];

    const int t  = threadIdx.x;
    const int tx = t & 15, ty = t >> 4;
    const int m0 = blockIdx.y * 64, n0 = blockIdx.x * 64;
    const int lr = t >> 2, lk = (t & 3) * 4;

    u64t acc2[4][2] = {};

    for (int k0 = 0; k0 < 512; k0 += 16) {
        float4 av = *(const float4*)(A + (m0 + lr) * 512 + k0 + lk);
        float4 bv = *(const float4*)(W + (n0 + lr) * 512 + k0 + lk);
        __syncthreads();
        As[lk+0][lr] = av.x; As[lk+1][lr] = av.y; As[lk+2][lr] = av.z; As[lk+3][lr] = av.w;
        Bs[lk+0][lr] = bv.x; Bs[lk+1][lr] = bv.y; Bs[lk+2][lr] = bv.z; Bs[lk+3][lr] = bv.w;
        __syncthreads();
#pragma unroll
        for (int k = 0; k < 16; k++) {
            float4 a4 = *(const float4*)&As[k][ty * 4];
            float4 b4 = *(const float4*)&Bs[k][tx * 4];
            const u64t b01 = pack2(b4.x, b4.y);
            const u64t b23 = pack2(b4.z, b4.w);
            float ar[4] = {a4.x, a4.y, a4.z, a4.w};
#pragma unroll
            for (int e = 0; e < 4; e++) {
                const u64t ae = pack2(ar[e], ar[e]);
                acc2[e][0] = fma2(ae, b01, acc2[e][0]);
                acc2[e][1] = fma2(ae, b23, acc2[e][1]);
            }
        }
    }
#pragma unroll
    for (int e = 0; e < 4; e++) {
        float4 v;
        unpack2(acc2[e][0], v.x, v.y);
        unpack2(acc2[e][1], v.z, v.w);
        *(float4*)(C + (m0 + ty * 4 + e) * 512 + n0 + tx * 4) = v;
    }
}

// ---------------------------------------------------------------------------
// Shift-SSM FIR on K (64 taps + skip), one block per channel
// ---------------------------------------------------------------------------
__global__ __launch_bounds__(256) void shift_conv(
    const float* __restrict__ Cs, const float* __restrict__ Ds)
{
    const int d = blockIdx.x;
    __shared__ float taps[64];
    __shared__ float col[1024];
    const int t = threadIdx.x;
    if (t < 64) taps[t] = Cs[d * 64 + t];
    for (int s = t; s < 1024; s += 256) col[s] = g_K0[s * 512 + d];
    __syncthreads();
    const float dsv = Ds[d];
    for (int s = t; s < 1024; s += 256) {
        float acc = dsv * col[s];
        const int tmax = (s < 63) ? s : 63;
        for (int tt = 0; tt <= tmax; tt++) acc += taps[tt] * col[s - tt];
        g_K[s * 512 + d] = acc;
    }
}

// ---------------------------------------------------------------------------
// S4D diagonal SSM scan + Q contraction.
// channel c = h*4096 + i*64 + j,  u[c,s] = K[s,h,i]*V[s,h,j]
//   z' = dA*z + u  (complex),  y = 2Re(sum_n CB*z) + Dd*u
//   O_t[h*64+j][s] = sum_i Q[s,h,i]*y[(h,i,j),s]
//
// grid = 512 (h,j); 256 threads: thread = (i = t>>2, nq = t&3 -> 16 modes).
// 8 packed complex pairs per thread, all math fma.rn.f32x2.
// Dual accumulators (accA: C2re*zre, accB: C2im*zim) remove the nC2im2
// register array so the kernel fits 128 regs -> 2 blocks/SM (4 warps/SMSP).
// ---------------------------------------------------------------------------
__global__ __launch_bounds__(256, 2) void scan_s4d(
    const float* __restrict__ Are, const float* __restrict__ Aim,
    const float* __restrict__ Cre, const float* __restrict__ Cim,
    const float* __restrict__ Dd)
{
    const int bx = blockIdx.x;
    const int h = bx >> 6, j = bx & 63;
    const int t = threadIdx.x;
    const int i = t >> 2, nq = t & 3, n0 = nq * 16;
    const int c = h * 4096 + i * 64 + j;
    const int lane = t & 31, warp = t >> 5;

    u64t dAre2[8], dAim2[8], ndAim2[8], C2re2[8], C2im2[8], zre2[8], zim2[8];

#pragma unroll
    for (int p = 0; p < 8; p++) {
        float dare[2], daim[2], c2re[2], c2im[2];
#pragma unroll
        for (int e = 0; e < 2; e++) {
            const int n = n0 + 2 * p + e;
            const float are = Are[n], aim = Aim[n];
            const float dre = 1.f - 0.05f * are, dim = -0.05f * aim;   // 1 - DT*A/2
            const float nre = 1.f + 0.05f * are, nim = 0.05f * aim;    // 1 + DT*A/2
            const float inv = 1.f / (dre * dre + dim * dim);
            dare[e] = (nre * dre + nim * dim) * inv;                   // dA
            daim[e] = (nim * dre - nre * dim) * inv;
            const float dbre = 0.1f * dre * inv;                       // dB = DT/d
            const float dbim = -0.1f * dim * inv;
            const float cr = Cre[c * 64 + n], ci = Cim[c * 64 + n];
            c2re[e] = 2.f * (cr * dbre - ci * dbim);                   // 2*CB
            c2im[e] = 2.f * (cr * dbim + ci * dbre);
        }
        dAre2[p]  = pack2(dare[0], dare[1]);
        dAim2[p]  = pack2(daim[0], daim[1]);
        ndAim2[p] = pack2(-daim[0], -daim[1]);
        C2re2[p]  = pack2(c2re[0], c2re[1]);
        C2im2[p]  = pack2(c2im[0], c2im[1]);
        zre2[p] = 0ull; zim2[p] = 0ull;
    }
    const float ddv = Dd[c];

    __shared__ __align__(16) float Qs[4096];   // [64 steps][64 i]
    __shared__ __align__(16) float Ks[4096];
    __shared__ float Vs[64];
    __shared__ float obuf[512];

    for (int ch = 0; ch < 16; ch++) {
        const int s0 = ch * 64;
        __syncthreads();
        for (int idx = t; idx < 4096; idx += 256) {
            const int r = idx >> 6, cc = idx & 63;
            Qs[idx] = g_Q[(s0 + r) * 512 + h * 64 + cc];
            Ks[idx] = g_K[(s0 + r) * 512 + h * 64 + cc];
        }
        if (t < 64) Vs[t] = g_V[(s0 + t) * 512 + h * 64 + j];
        __syncthreads();

#pragma unroll 2
        for (int r = 0; r < 64; r++) {
            const float u  = Ks[r * 64 + i] * Vs[r];
            const u64t u2  = pack2(u, u);
            u64t accA = 0ull, accB = 0ull;
#pragma unroll
            for (int p = 0; p < 8; p++) {
                // zre' = dre*zre - dim*zim + u ; zim' = dre*zim + dim*zre
                const u64t a = fma2(ndAim2[p], zim2[p], u2);
                const u64t b = mul2(dAim2[p], zre2[p]);
                zim2[p] = fma2(dAre2[p], zim2[p], b);
                zre2[p] = fma2(dAre2[p], zre2[p], a);
                accA = fma2(C2re2[p], zre2[p], accA);
                accB = fma2(C2im2[p], zim2[p], accB);
            }
            float alo, ahi, blo, bhi;
            unpack2(accA, alo, ahi);
            unpack2(accB, blo, bhi);
            float yp = (alo + ahi) - (blo + bhi);
            // reduce over the 4 n-quarters of channel c
            yp += __shfl_xor_sync(0xffffffffu, yp, 1);
            yp += __shfl_xor_sync(0xffffffffu, yp, 2);
            // y[c] complete -> weight by Q[s,h,i] (+ skip term)
            float val = (yp + ddv * u) * Qs[r * 64 + i];
            // reduce over the 8 i's in this warp
            val += __shfl_xor_sync(0xffffffffu, val, 4);
            val += __shfl_xor_sync(0xffffffffu, val, 8);
            val += __shfl_xor_sync(0xffffffffu, val, 16);
            if (lane == 0) obuf[r * 8 + warp] = val;
        }
        __syncthreads();
        if (t < 64) {
            float o = 0.f;
#pragma unroll
            for (int w = 0; w < 8; w++) o += obuf[t * 8 + w];
            g_Ot[(h * 64 + j) * 1024 + s0 + t] = o;   // coalesced: [d][s]
        }
    }
}

// ---------------------------------------------------------------------------
// GEMM 2: out[s,n] = sum_k g_Ot[k][s] * WO[n,k]
// ---------------------------------------------------------------------------
__global__ __launch_bounds__(256) void gemm_out(
    const float* __restrict__ WO, float* __restrict__ out)
{
    __shared__ __align__(16) float As[16][64];
    __shared__ __align__(16) float Bs[16][64];

    const int t  = threadIdx.x;
    const int tx = t & 15, ty = t >> 4;
    const int m0 = blockIdx.y * 64, n0 = blockIdx.x * 64;
    const int lr = t >> 2, lk = (t & 3) * 4;
    const int kk = t >> 4, mm = (t & 15) * 4;

    u64t acc2[4][2] = {};

    for (int k0 = 0; k0 < 512; k0 += 16) {
        float4 av = *(const float4*)(g_Ot + (k0 + kk) * 1024 + m0 + mm);
        float4 bv = *(const float4*)(WO + (n0 + lr) * 512 + k0 + lk);
        __syncthreads();
        *(float4*)&As[kk][mm] = av;  // already [k][m]
        Bs[lk+0][lr] = bv.x; Bs[lk+1][lr] = bv.y; Bs[lk+2][lr] = bv.z; Bs[lk+3][lr] = bv.w;
        __syncthreads();
#pragma unroll
        for (int k = 0; k < 16; k++) {
            float4 a4 = *(const float4*)&As[k][ty * 4];
            float4 b4 = *(const float4*)&Bs[k][tx * 4];
            const u64t b01 = pack2(b4.x, b4.y);
            const u64t b23 = pack2(b4.z, b4.w);
            float ar[4] = {a4.x, a4.y, a4.z, a4.w};
#pragma unroll
            for (int e = 0; e < 4; e++) {
                const u64t ae = pack2(ar[e], ar[e]);
                acc2[e][0] = fma2(ae, b01, acc2[e][0]);
                acc2[e][1] = fma2(ae, b23, acc2[e][1]);
            }
        }
    }
#pragma unroll
    for (int e = 0; e < 4; e++) {
        float4 v;
        unpack2(acc2[e][0], v.x, v.y);
        unpack2(acc2[e][1], v.z, v.w);
        *(float4*)(out + (m0 + ty * 4 + e) * 512 + n0 + tx * 4) = v;
    }
}

// ---------------------------------------------------------------------------
extern "C" void kernel_launch(void* const* d_in, const int* in_sizes, int n_in,
                              void* d_out, int out_size)
{
    (void)in_sizes; (void)n_in; (void)out_size;
    const float* x   = (const float*)d_in[0];
    const float* WQ  = (const float*)d_in[1];
    const float* WK  = (const float*)d_in[2];
    const float* WV  = (const float*)d_in[3];
    const float* WO  = (const float*)d_in[4];
    const float* Cs  = (const float*)d_in[5];
    const float* Ds  = (const float*)d_in[6];
    const float* Are = (const float*)d_in[7];
    const float* Aim = (const float*)d_in[8];
    const float* Cre = (const float*)d_in[9];
    const float* Cim = (const float*)d_in[10];
    const float* Ddg = (const float*)d_in[11];

    gemm_qkv  <<<dim3(8, 16, 3), 256>>>(x, WQ, WK, WV);
    shift_conv<<<512, 256>>>(Cs, Ds);
    scan_s4d  <<<512, 256>>>(Are, Aim, Cre, Cim, Ddg);
    gemm_out  <<<dim3(8, 16), 256>>>(WO, (float*)d_out);
}

// round 12
// speedup vs baseline: 6.0468x; 1.1446x over previous
#include <cuda_runtime.h>

// ---------------------------------------------------------------------------
// H3 block: Q/K/V proj -> shift-SSM FIR on K -> per-head KV outer product ->
// S4D diagonal SSM (linear recurrence scan, packed f32x2) -> Q contraction ->
// output projection.  B=1, S=1024, D=512, HEADS=8, DH=64, N=64, DT=0.1
// ---------------------------------------------------------------------------

#define SQ   1024
#define DD   512

__device__ float g_Q [SQ*DD];
__device__ float g_K0[SQ*DD];
__device__ float g_K [SQ*DD];
__device__ float g_V [SQ*DD];
__device__ float g_Ot[DD*SQ];   // pre-WO output, transposed [d][s]

typedef unsigned long long u64t;

__device__ __forceinline__ u64t pack2(float lo, float hi) {
    u64t r; asm("mov.b64 %0, {%1,%2};" : "=l"(r) : "f"(lo), "f"(hi)); return r;
}
__device__ __forceinline__ void unpack2(u64t v, float& lo, float& hi) {
    asm("mov.b64 {%0,%1}, %2;" : "=f"(lo), "=f"(hi) : "l"(v));
}
__device__ __forceinline__ u64t fma2(u64t a, u64t b, u64t c) {
    u64t d; asm("fma.rn.f32x2 %0, %1, %2, %3;" : "=l"(d) : "l"(a), "l"(b), "l"(c)); return d;
}
__device__ __forceinline__ u64t mul2(u64t a, u64t b) {
    u64t d; asm("mul.rn.f32x2 %0, %1, %2;" : "=l"(d) : "l"(a), "l"(b)); return d;
}

// ---------------------------------------------------------------------------
// GEMM 1: C[1024,512] = A @ W^T  (x3 via grid.z), 64x64 tile, packed-f32x2 FMA
// ---------------------------------------------------------------------------
__global__ __launch_bounds__(256) void gemm_qkv(
    const float* __restrict__ A,
    const float* __restrict__ WQ, const float* __restrict__ WK,
    const float* __restrict__ WV)
{
    const float* W = (blockIdx.z == 0) ? WQ : (blockIdx.z == 1) ? WK : WV;
    float*       C = (blockIdx.z == 0) ? g_Q : (blockIdx.z == 1) ? g_K0 : g_V;

    __shared__ __align__(16) float As[16][64];
    __shared__ __align__(16) float Bs[16][64];

    const int t  = threadIdx.x;
    const int tx = t & 15, ty = t >> 4;
    const int m0 = blockIdx.y * 64, n0 = blockIdx.x * 64;
    const int lr = t >> 2, lk = (t & 3) * 4;

    u64t acc2[4][2] = {};

    for (int k0 = 0; k0 < 512; k0 += 16) {
        float4 av = *(const float4*)(A + (m0 + lr) * 512 + k0 + lk);
        float4 bv = *(const float4*)(W + (n0 + lr) * 512 + k0 + lk);
        __syncthreads();
        As[lk+0][lr] = av.x; As[lk+1][lr] = av.y; As[lk+2][lr] = av.z; As[lk+3][lr] = av.w;
        Bs[lk+0][lr] = bv.x; Bs[lk+1][lr] = bv.y; Bs[lk+2][lr] = bv.z; Bs[lk+3][lr] = bv.w;
        __syncthreads();
#pragma unroll
        for (int k = 0; k < 16; k++) {
            float4 a4 = *(const float4*)&As[k][ty * 4];
            float4 b4 = *(const float4*)&Bs[k][tx * 4];
            const u64t b01 = pack2(b4.x, b4.y);
            const u64t b23 = pack2(b4.z, b4.w);
            float ar[4] = {a4.x, a4.y, a4.z, a4.w};
#pragma unroll
            for (int e = 0; e < 4; e++) {
                const u64t ae = pack2(ar[e], ar[e]);
                acc2[e][0] = fma2(ae, b01, acc2[e][0]);
                acc2[e][1] = fma2(ae, b23, acc2[e][1]);
            }
        }
    }
#pragma unroll
    for (int e = 0; e < 4; e++) {
        float4 v;
        unpack2(acc2[e][0], v.x, v.y);
        unpack2(acc2[e][1], v.z, v.w);
        *(float4*)(C + (m0 + ty * 4 + e) * 512 + n0 + tx * 4) = v;
    }
}

// ---------------------------------------------------------------------------
// Shift-SSM FIR on K (64 taps + skip), one block per channel
// ---------------------------------------------------------------------------
__global__ __launch_bounds__(256) void shift_conv(
    const float* __restrict__ Cs, const float* __restrict__ Ds)
{
    const int d = blockIdx.x;
    __shared__ float taps[64];
    __shared__ float col[1024];
    const int t = threadIdx.x;
    if (t < 64) taps[t] = Cs[d * 64 + t];
    for (int s = t; s < 1024; s += 256) col[s] = g_K0[s * 512 + d];
    __syncthreads();
    const float dsv = Ds[d];
    for (int s = t; s < 1024; s += 256) {
        float acc = dsv * col[s];
        const int tmax = (s < 63) ? s : 63;
        for (int tt = 0; tt <= tmax; tt++) acc += taps[tt] * col[s - tt];
        g_K[s * 512 + d] = acc;
    }
}

// ---------------------------------------------------------------------------
// S4D diagonal SSM scan + Q contraction, batched reduction.
// channel c = h*4096 + i*64 + j,  u[c,s] = K[s,h,i]*V[s,h,j]
//   z' = dA*z + u  (complex),  y = 2Re(sum_n CB*z) + Dd*u
//   O_t[h*64+j][s] = sum_i Q[s,h,i]*y[(h,i,j),s]
//
// grid = 512 (h,j); 256 threads: thread = (i = t>>2, nq = t&3 -> 16 modes).
// 8 packed complex pairs per thread; all recurrence math fma.rn.f32x2.
// NO per-step shuffles: each thread folds Q into its quarter-partial
//   val = yp_quarter * Q[r,i]  (+ Q*Dd*u on nq==0)
// and stages it; every 16 steps one block-wide reduce pass sums 256
// partials per step (16 LDS + 4 SHFL per thread).
// ---------------------------------------------------------------------------
__global__ __launch_bounds__(256) void scan_s4d(
    const float* __restrict__ Are, const float* __restrict__ Aim,
    const float* __restrict__ Cre, const float* __restrict__ Cim,
    const float* __restrict__ Dd)
{
    const int bx = blockIdx.x;
    const int h = bx >> 6, j = bx & 63;
    const int t = threadIdx.x;
    const int i = t >> 2, nq = t & 3, n0 = nq * 16;
    const int c = h * 4096 + i * 64 + j;

    u64t dAre2[8], dAim2[8], ndAim2[8], C2re2[8], C2im2[8], zre2[8], zim2[8];

#pragma unroll
    for (int p = 0; p < 8; p++) {
        float dare[2], daim[2], c2re[2], c2im[2];
#pragma unroll
        for (int e = 0; e < 2; e++) {
            const int n = n0 + 2 * p + e;
            const float are = Are[n], aim = Aim[n];
            const float dre = 1.f - 0.05f * are, dim = -0.05f * aim;   // 1 - DT*A/2
            const float nre = 1.f + 0.05f * are, nim = 0.05f * aim;    // 1 + DT*A/2
            const float inv = 1.f / (dre * dre + dim * dim);
            dare[e] = (nre * dre + nim * dim) * inv;                   // dA
            daim[e] = (nim * dre - nre * dim) * inv;
            const float dbre = 0.1f * dre * inv;                       // dB = DT/d
            const float dbim = -0.1f * dim * inv;
            const float cr = Cre[c * 64 + n], ci = Cim[c * 64 + n];
            c2re[e] = 2.f * (cr * dbre - ci * dbim);                   // 2*CB
            c2im[e] = 2.f * (cr * dbim + ci * dbre);
        }
        dAre2[p]  = pack2(dare[0], dare[1]);
        dAim2[p]  = pack2(daim[0], daim[1]);
        ndAim2[p] = pack2(-daim[0], -daim[1]);
        C2re2[p]  = pack2(c2re[0], c2re[1]);
        C2im2[p]  = pack2(c2im[0], c2im[1]);
        zre2[p] = 0ull; zim2[p] = 0ull;
    }
    const float ddv = (nq == 0) ? Dd[c] : 0.f;

    __shared__ __align__(16) float Qs[4096];   // [64 steps][64 i]
    __shared__ __align__(16) float Ks[4096];
    __shared__ float Vs[64];
    __shared__ float sVals[16 * 257];          // [16 steps][256 threads], pad

    for (int ch = 0; ch < 16; ch++) {
        const int s0 = ch * 64;
        __syncthreads();
        for (int idx = t; idx < 4096; idx += 256) {
            const int r = idx >> 6, cc = idx & 63;
            Qs[idx] = g_Q[(s0 + r) * 512 + h * 64 + cc];
            Ks[idx] = g_K[(s0 + r) * 512 + h * 64 + cc];
        }
        if (t < 64) Vs[t] = g_V[(s0 + t) * 512 + h * 64 + j];
        __syncthreads();

        for (int g = 0; g < 4; g++) {
#pragma unroll
            for (int rr = 0; rr < 16; rr++) {
                const int r = g * 16 + rr;
                const float u  = Ks[r * 64 + i] * Vs[r];
                const u64t u2  = pack2(u, u);
                u64t accA = 0ull, accB = 0ull;
#pragma unroll
                for (int p = 0; p < 8; p++) {
                    // zre' = dre*zre - dim*zim + u ; zim' = dre*zim + dim*zre
                    const u64t a = fma2(ndAim2[p], zim2[p], u2);
                    const u64t b = mul2(dAim2[p], zre2[p]);
                    zim2[p] = fma2(dAre2[p], zim2[p], b);
                    zre2[p] = fma2(dAre2[p], zre2[p], a);
                    accA = fma2(C2re2[p], zre2[p], accA);
                    accB = fma2(C2im2[p], zim2[p], accB);
                }
                float alo, ahi, blo, bhi;
                unpack2(accA, alo, ahi);
                unpack2(accB, blo, bhi);
                const float yp = (alo + ahi) - (blo + bhi);
                const float q  = Qs[r * 64 + i];
                // quarter-partial with Q folded in; skip term only on nq==0
                sVals[rr * 257 + t] = (yp + ddv * u) * q;
            }
            __syncthreads();
            {   // reduce 256 partials for each of 16 steps
                const int r = t >> 4, part = t & 15;
                const float* row = sVals + r * 257 + part;
                float s = 0.f;
#pragma unroll
                for (int m = 0; m < 16; m++) s += row[16 * m];
                s += __shfl_xor_sync(0xffffffffu, s, 1);
                s += __shfl_xor_sync(0xffffffffu, s, 2);
                s += __shfl_xor_sync(0xffffffffu, s, 4);
                s += __shfl_xor_sync(0xffffffffu, s, 8);
                if (part == 0)
                    g_Ot[(h * 64 + j) * 1024 + s0 + g * 16 + r] = s;
            }
            __syncthreads();
        }
    }
}

// ---------------------------------------------------------------------------
// GEMM 2: out[s,n] = sum_k g_Ot[k][s] * WO[n,k]
// ---------------------------------------------------------------------------
__global__ __launch_bounds__(256) void gemm_out(
    const float* __restrict__ WO, float* __restrict__ out)
{
    __shared__ __align__(16) float As[16][64];
    __shared__ __align__(16) float Bs[16][64];

    const int t  = threadIdx.x;
    const int tx = t & 15, ty = t >> 4;
    const int m0 = blockIdx.y * 64, n0 = blockIdx.x * 64;
    const int lr = t >> 2, lk = (t & 3) * 4;
    const int kk = t >> 4, mm = (t & 15) * 4;

    u64t acc2[4][2] = {};

    for (int k0 = 0; k0 < 512; k0 += 16) {
        float4 av = *(const float4*)(g_Ot + (k0 + kk) * 1024 + m0 + mm);
        float4 bv = *(const float4*)(WO + (n0 + lr) * 512 + k0 + lk);
        __syncthreads();
        *(float4*)&As[kk][mm] = av;  // already [k][m]
        Bs[lk+0][lr] = bv.x; Bs[lk+1][lr] = bv.y; Bs[lk+2][lr] = bv.z; Bs[lk+3][lr] = bv.w;
        __syncthreads();
#pragma unroll
        for (int k = 0; k < 16; k++) {
            float4 a4 = *(const float4*)&As[k][ty * 4];
            float4 b4 = *(const float4*)&Bs[k][tx * 4];
            const u64t b01 = pack2(b4.x, b4.y);
            const u64t b23 = pack2(b4.z, b4.w);
            float ar[4] = {a4.x, a4.y, a4.z, a4.w};
#pragma unroll
            for (int e = 0; e < 4; e++) {
                const u64t ae = pack2(ar[e], ar[e]);
                acc2[e][0] = fma2(ae, b01, acc2[e][0]);
                acc2[e][1] = fma2(ae, b23, acc2[e][1]);
            }
        }
    }
#pragma unroll
    for (int e = 0; e < 4; e++) {
        float4 v;
        unpack2(acc2[e][0], v.x, v.y);
        unpack2(acc2[e][1], v.z, v.w);
        *(float4*)(out + (m0 + ty * 4 + e) * 512 + n0 + tx * 4) = v;
    }
}

// ---------------------------------------------------------------------------
extern "C" void kernel_launch(void* const* d_in, const int* in_sizes, int n_in,
                              void* d_out, int out_size)
{
    (void)in_sizes; (void)n_in; (void)out_size;
    const float* x   = (const float*)d_in[0];
    const float* WQ  = (const float*)d_in[1];
    const float* WK  = (const float*)d_in[2];
    const float* WV  = (const float*)d_in[3];
    const float* WO  = (const float*)d_in[4];
    const float* Cs  = (const float*)d_in[5];
    const float* Ds  = (const float*)d_in[6];
    const float* Are = (const float*)d_in[7];
    const float* Aim = (const float*)d_in[8];
    const float* Cre = (const float*)d_in[9];
    const float* Cim = (const float*)d_in[10];
    const float* Ddg = (const float*)d_in[11];

    gemm_qkv  <<<dim3(8, 16, 3), 256>>>(x, WQ, WK, WV);
    shift_conv<<<512, 256>>>(Cs, Ds);
    scan_s4d  <<<512, 256>>>(Are, Aim, Cre, Cim, Ddg);
    gemm_out  <<<dim3(8, 16), 256>>>(WO, (float*)d_out);
}